// round 15
// baseline (speedup 1.0000x reference)
#include <cuda_runtime.h>
#include <cuda_bf16.h>

#define BB      8
#define NN      4096
#define CC      64
#define KD      32
#define KEXT    48
#define KOUT    16
#define NCT     32
#define ROWB    144          // padded smem row stride (bytes) for 128B rows

// K1 smem layout (bytes)
#define SA      0                    // 128*144 = 18432
#define SB0     18432
#define SB1     36864
#define SSTAGE  55296                // 128*128 f32 = 65536
#define K1_SMEM 120832

__device__ float g_sqc[BB * NN];
__device__ float g_adjT[(size_t)BB * NN * NN];          // [b][c][q] approx
__device__ __nv_bfloat16 g_bf[(size_t)BB * NN * CC];
__device__ unsigned int g_cand[(size_t)BB * NN * KEXT];

__device__ __forceinline__ unsigned int ord32(float f) {
    unsigned int b = __float_as_uint(f);
    return b ^ ((b & 0x80000000u) ? 0xFFFFFFFFu : 0x80000000u);
}
__device__ __forceinline__ float iord32(unsigned int y) {
    unsigned int b = (y & 0x80000000u) ? (y ^ 0x80000000u) : ~y;
    return __uint_as_float(b);
}
__device__ __forceinline__ void cpa16(unsigned int smem_dst, const void* gsrc) {
    asm volatile("cp.async.cg.shared.global [%0], [%1], 16;" :: "r"(smem_dst), "l"(gsrc));
}
#define CP_COMMIT() asm volatile("cp.async.commit_group;")
#define CP_WAIT0()  asm volatile("cp.async.wait_group 0;")

__device__ __forceinline__ void mma16816(float* d, const unsigned int* a,
                                         const unsigned int* b) {
    asm volatile(
        "mma.sync.aligned.m16n8k16.row.col.f32.bf16.bf16.f32 "
        "{%0,%1,%2,%3}, {%4,%5,%6,%7}, {%8,%9}, {%0,%1,%2,%3};"
        : "+f"(d[0]), "+f"(d[1]), "+f"(d[2]), "+f"(d[3])
        : "r"(a[0]), "r"(a[1]), "r"(a[2]), "r"(a[3]), "r"(b[0]), "r"(b[1]));
}

// ---- prep: bf16 round + exact XLA-order squared norms ----
__global__ void __launch_bounds__(256) prep_kernel(const float* __restrict__ pts) {
    int i = blockIdx.x * 256 + threadIdx.x;
    const float4* g4 = (const float4*)(pts + (size_t)i * CC);
    __nv_bfloat162* o = (__nv_bfloat162*)(g_bf + (size_t)i * CC);
    float a[32];
    #pragma unroll
    for (int t = 0; t < 16; ++t) {
        float4 v = g4[t];
        a[2 * t]     = __fadd_rn(__fmul_rn(v.x, v.x), __fmul_rn(v.y, v.y));
        a[2 * t + 1] = __fadd_rn(__fmul_rn(v.z, v.z), __fmul_rn(v.w, v.w));
        o[2 * t]     = __nv_bfloat162(__float2bfloat16_rn(v.x), __float2bfloat16_rn(v.y));
        o[2 * t + 1] = __nv_bfloat162(__float2bfloat16_rn(v.z), __float2bfloat16_rn(v.w));
    }
    #pragma unroll
    for (int off = 16; off >= 1; off >>= 1)
        #pragma unroll
        for (int l = 0; l < 16; ++l)
            if (l < off) a[l] = __fadd_rn(a[l], a[l + off]);
    g_sqc[i] = a[0];
}

// ---- K1: bf16 HMMA GEMM -> approx adjT[b][c][q] ----
__global__ void __launch_bounds__(256, 1)
adj_mma_kernel()
{
    extern __shared__ char smem[];
    const unsigned int smb = (unsigned int)__cvta_generic_to_shared(smem);
    float* stage = (float*)(smem + SSTAGE);

    const int tid  = threadIdx.x;
    const int wid  = tid >> 5;
    const int lane = tid & 31;
    const int wy = wid >> 2;          // 0..1
    const int wx = wid & 3;           // 0..3
    const int g  = lane >> 2;         // 0..7
    const int t  = lane & 3;          // 0..3

    const int b     = blockIdx.y;
    const int qbase = blockIdx.x * 128;
    const char* bfB = (const char*)(g_bf + (size_t)b * NN * CC);
    const float* sqB = g_sqc + b * NN;

    // load A tile (128 rows x 128B) + B tile 0
    #pragma unroll
    for (int i = 0; i < 4; ++i) {
        int idx = i * 256 + tid;          // 0..1023
        int row = idx >> 3, gr = idx & 7;
        cpa16(smb + SA + row * ROWB + gr * 16,
              bfB + (size_t)(qbase + row) * 128 + gr * 16);
    }
    #pragma unroll
    for (int i = 0; i < 4; ++i) {
        int idx = i * 256 + tid;
        int row = idx >> 3, gr = idx & 7;
        cpa16(smb + SB0 + row * ROWB + gr * 16, bfB + (size_t)row * 128 + gr * 16);
    }
    CP_COMMIT();

    float sqQv[4][2];
    #pragma unroll
    for (int m = 0; m < 4; ++m) {
        int q0 = qbase + wy * 64 + m * 16 + g;
        sqQv[m][0] = __ldg(sqB + q0);
        sqQv[m][1] = __ldg(sqB + q0 + 8);
    }

    CP_WAIT0();
    __syncthreads();

    float* outB = g_adjT + ((size_t)b << 24);

    for (int ct = 0; ct < NCT; ++ct) {
        const int cbase = ct * 128;
        const unsigned int sbCur = smb + ((ct & 1) ? SB1 : SB0);

        if (ct + 1 < NCT) {
            const unsigned int sbNxt = smb + ((ct & 1) ? SB0 : SB1);
            const char* src = bfB + (size_t)(cbase + 128) * 128;
            #pragma unroll
            for (int i = 0; i < 4; ++i) {
                int idx = i * 256 + tid;
                int row = idx >> 3, gr = idx & 7;
                cpa16(sbNxt + row * ROWB + gr * 16, src + (size_t)row * 128 + gr * 16);
            }
            CP_COMMIT();
        }

        float d[4][4][4];
        #pragma unroll
        for (int m = 0; m < 4; ++m)
            #pragma unroll
            for (int n = 0; n < 4; ++n)
                #pragma unroll
                for (int r = 0; r < 4; ++r) d[m][n][r] = 0.0f;

        #pragma unroll
        for (int ks = 0; ks < 4; ++ks) {
            unsigned int afr[4][4];
            #pragma unroll
            for (int m = 0; m < 4; ++m) {
                unsigned int base = smb + SA + (wy * 64 + m * 16 + g) * ROWB + ks * 32 + t * 4;
                asm volatile("ld.shared.b32 %0, [%1];" : "=r"(afr[m][0]) : "r"(base));
                asm volatile("ld.shared.b32 %0, [%1];" : "=r"(afr[m][1]) : "r"(base + 8 * ROWB));
                asm volatile("ld.shared.b32 %0, [%1];" : "=r"(afr[m][2]) : "r"(base + 16));
                asm volatile("ld.shared.b32 %0, [%1];" : "=r"(afr[m][3]) : "r"(base + 8 * ROWB + 16));
            }
            unsigned int bfr[4][2];
            #pragma unroll
            for (int n = 0; n < 4; ++n) {
                unsigned int base = sbCur + (wx * 32 + n * 8 + g) * ROWB + ks * 32 + t * 4;
                asm volatile("ld.shared.b32 %0, [%1];" : "=r"(bfr[n][0]) : "r"(base));
                asm volatile("ld.shared.b32 %0, [%1];" : "=r"(bfr[n][1]) : "r"(base + 16));
            }
            #pragma unroll
            for (int m = 0; m < 4; ++m)
                #pragma unroll
                for (int n = 0; n < 4; ++n)
                    mma16816(d[m][n], afr[m], bfr[n]);
        }

        // epilogue: approx adj, stage transposed, coalesced store
        const float* sqcB = sqB + cbase;
        #pragma unroll
        for (int n = 0; n < 4; ++n) {
            int c0 = wx * 32 + n * 8 + 2 * t;
            float sc0 = __ldg(sqcB + c0);
            float sc1 = __ldg(sqcB + c0 + 1);
            #pragma unroll
            for (int m = 0; m < 4; ++m) {
                int q0 = wy * 64 + m * 16 + g;
                float a00 = __fadd_rn(fmaf(-2.0f, d[m][n][0], sqQv[m][0]), sc0);
                float a01 = __fadd_rn(fmaf(-2.0f, d[m][n][1], sqQv[m][0]), sc1);
                float a10 = __fadd_rn(fmaf(-2.0f, d[m][n][2], sqQv[m][1]), sc0);
                float a11 = __fadd_rn(fmaf(-2.0f, d[m][n][3], sqQv[m][1]), sc1);
                stage[c0 * 128       + ((q0)     ^ (((c0)     & 7) << 2))] = a00;
                stage[(c0 + 1) * 128 + ((q0)     ^ (((c0 + 1) & 7) << 2))] = a01;
                stage[c0 * 128       + ((q0 + 8) ^ (((c0)     & 7) << 2))] = a10;
                stage[(c0 + 1) * 128 + ((q0 + 8) ^ (((c0 + 1) & 7) << 2))] = a11;
            }
        }
        __syncthreads();

        #pragma unroll
        for (int i = 0; i < 16; ++i) {
            int idx = i * 256 + tid;
            int row = idx >> 5;
            int c4  = idx & 31;
            float4 v = *(const float4*)(stage + row * 128 + ((c4 ^ (row & 7)) << 2));
            *(float4*)(outB + ((size_t)(cbase + row) << 12) + qbase + (c4 << 2)) = v;
        }

        if (ct + 1 < NCT) CP_WAIT0();
        __syncthreads();
    }
}

// ---- K2: streaming approx top-48 filter, writes candidate indices ----
__global__ void __launch_bounds__(128)
select_kernel()
{
    extern __shared__ unsigned long long topk[];   // 128 * KEXT

    const int tid   = threadIdx.x;
    const int b     = blockIdx.y;
    const int qbase = blockIdx.x * 128;
    const int q     = qbase + tid;

    unsigned long long* row = topk + tid * KEXT;
    #pragma unroll
    for (int i = 0; i < KEXT; ++i) row[i] = 0xFFFFFFFFFFFFFFFFull;

    const float* col = g_adjT + ((size_t)b << 24) + q;
    float thr = iord32(0xFFFFFFFFu);

    float buf[4][8];
    #pragma unroll
    for (int pb = 0; pb < 3; ++pb)
        #pragma unroll
        for (int u = 0; u < 8; ++u)
            buf[pb][u] = col[(size_t)(pb * 8 + u) << 12];

    #pragma unroll 1
    for (int c8 = 0; c8 < NN; c8 += 8) {
        int stg = (c8 >> 3) & 3;
        if (c8 + 24 < NN) {
            int pre = (stg + 3) & 3;
            #pragma unroll
            for (int u = 0; u < 8; ++u)
                buf[pre][u] = col[(size_t)(c8 + 24 + u) << 12];
        }
        float av[8];
        #pragma unroll
        for (int u = 0; u < 8; ++u) av[u] = buf[stg][u];

        float mn = fminf(fminf(fminf(av[0], av[1]), fminf(av[2], av[3])),
                         fminf(fminf(av[4], av[5]), fminf(av[6], av[7])));
        if (mn > thr) continue;
        #pragma unroll
        for (int u = 0; u < 8; ++u) {
            if (av[u] > thr) continue;
            unsigned long long key =
                ((unsigned long long)ord32(av[u]) << 32) |
                (unsigned int)(c8 + u);
            if (key < row[KEXT - 1]) {
                int p = KEXT - 1;
                while (p > 0 && row[p - 1] > key) { row[p] = row[p - 1]; --p; }
                row[p] = key;
                thr = iord32((unsigned int)(row[KEXT - 1] >> 32));
            }
        }
    }

    unsigned int* cd = g_cand + ((size_t)b * NN + q) * KEXT;
    #pragma unroll
    for (int i = 0; i < KEXT; ++i)
        cd[i] = (unsigned int)(row[i] & 0xFFFFFFFFull);
}

// ---- K3: exact re-rank of 48 survivors (bit-exact R2 keys) + output ----
__global__ void __launch_bounds__(128)
rerank_kernel(const float* __restrict__ xyz,
              const float* __restrict__ pts,
              float* __restrict__ out)
{
    __shared__ unsigned long long topk[128 * KD];   // 32KB

    const int tid   = threadIdx.x;
    const int b     = blockIdx.y;
    const int qbase = blockIdx.x * 128;
    const int q     = qbase + tid;
    const float* ptsB = pts + (size_t)b * NN * CC;
    const float* sqB  = g_sqc + b * NN;

    unsigned long long* row = topk + tid * KD;
    #pragma unroll
    for (int i = 0; i < KD; ++i) row[i] = 0xFFFFFFFFFFFFFFFFull;

    // query vector into registers
    float xq[CC];
    {
        const float4* g4 = (const float4*)(ptsB + (size_t)q * CC);
        #pragma unroll
        for (int i = 0; i < 16; ++i) {
            float4 v = __ldg(g4 + i);
            xq[4 * i] = v.x; xq[4 * i + 1] = v.y; xq[4 * i + 2] = v.z; xq[4 * i + 3] = v.w;
        }
    }
    const float sqQ = __ldg(sqB + q);

    const unsigned int* cd = g_cand + ((size_t)b * NN + q) * KEXT;

    #pragma unroll 1
    for (int j = 0; j < KEXT; ++j) {
        unsigned int idx = __ldg(cd + j);
        const float4* y4 = (const float4*)(ptsB + (size_t)idx * CC);
        float yv[CC];
        #pragma unroll
        for (int i = 0; i < 16; ++i) {
            float4 v = __ldg(y4 + i);
            yv[4 * i] = v.x; yv[4 * i + 1] = v.y; yv[4 * i + 2] = v.z; yv[4 * i + 3] = v.w;
        }
        // exact inner: ascending-k fp32 fma chain (matches cuBLAS / R2 bit-exactly)
        float inner = 0.0f;
        #pragma unroll
        for (int k = 0; k < CC; ++k) inner = fmaf(xq[k], yv[k], inner);
        float adj = __fadd_rn(fmaf(-2.0f, inner, sqQ), __ldg(sqB + idx));
        unsigned long long key =
            ((unsigned long long)ord32(adj) << 32) | idx;
        if (key < row[KD - 1]) {
            int p = KD - 1;
            while (p > 0 && row[p - 1] > key) { row[p] = row[p - 1]; --p; }
            row[p] = key;
        }
    }

    // ---- gather epilogue (dilation 2: even ranks)
    const float* xyzB = xyz + (size_t)b * NN * 3;
    const float* xb = xyzB + (size_t)q * 3;
    float x0 = xb[0], x1 = xb[1], x2 = xb[2];
    float* o = out + (((size_t)b * NN + q) * KOUT) * 10;
    #pragma unroll 4
    for (int j = 0; j < KOUT; ++j) {
        unsigned int idx = (unsigned int)(row[2 * j] & 0xFFFFFFFFull);
        const float* nb = xyzB + (size_t)idx * 3;
        float n0 = nb[0], n1 = nb[1], n2 = nb[2];
        float r0 = x0 - n0, r1 = x1 - n1, r2 = x2 - n2;
        float d  = sqrtf(r0 * r0 + r1 * r1 + r2 * r2);
        float* oj = o + j * 10;
        oj[0] = d;
        oj[1] = r0; oj[2] = r1; oj[3] = r2;
        oj[4] = x0; oj[5] = x1; oj[6] = x2;
        oj[7] = n0; oj[8] = n1; oj[9] = n2;
    }
}

extern "C" void kernel_launch(void* const* d_in, const int* in_sizes, int n_in,
                              void* d_out, int out_size) {
    const float* in0 = (const float*)d_in[0];
    const float* in1 = (const float*)d_in[1];
    const float* xyz;
    const float* pts;
    if (in_sizes[0] == BB * NN * 3) { xyz = in0; pts = in1; }
    else                            { xyz = in1; pts = in0; }

    cudaFuncSetAttribute(adj_mma_kernel,
                         cudaFuncAttributeMaxDynamicSharedMemorySize, K1_SMEM);
    cudaFuncSetAttribute(select_kernel,
                         cudaFuncAttributeMaxDynamicSharedMemorySize, 128 * KEXT * 8);

    prep_kernel<<<BB * NN / 256, 256>>>(pts);

    dim3 g1(NN / 128, BB);
    adj_mma_kernel<<<g1, 256, K1_SMEM>>>();

    dim3 g2(NN / 128, BB);
    select_kernel<<<g2, 128, 128 * KEXT * 8>>>();

    rerank_kernel<<<g2, 128>>>(xyz, pts, (float*)d_out);
}

// round 16
// speedup vs baseline: 1.1830x; 1.1830x over previous
#include <cuda_runtime.h>

#define BB      8
#define NN      4096
#define CC      64
#define KD      32
#define KEXT    48
#define KOUT    16
#define NCT     32

typedef unsigned int u32;
typedef unsigned long long u64;

// K1 smem layout (bytes)
#define SA      0        // A tile u32[16][128] = 8192
#define SB0     8192
#define SB1     16384
#define SM0     24576    // sqc 512 + scale 512
#define SM1     25600
#define STG_    26624    // stage u32[128][128] = 65536
#define K1_SMEM 92160

// K3 smem layout (bytes)
#define R_KEYS  0                    // u64[128*48] = 49152
#define R_ROWS  49152                // u64[128*32] = 32768
#define R_XQ    81920                // f32[128*64] = 32768
#define K3_SMEM 114688

__device__ float g_sqc[BB * NN];
__device__ float g_scale[BB * NN];
__device__ u32   g_q8T[(size_t)BB * NN * 16];        // [b][tile][k4][128] u32
__device__ u32   g_key[(size_t)BB * NN * NN];        // [b][c][q] packed keys (512MB)
__device__ u32   g_cand[(size_t)BB * NN * KEXT];

__device__ __forceinline__ u32 ord32(float f) {
    u32 b = __float_as_uint(f);
    return b ^ ((b & 0x80000000u) ? 0xFFFFFFFFu : 0x80000000u);
}
__device__ __forceinline__ void cpa16(u32 smem_dst, const void* gsrc) {
    asm volatile("cp.async.cg.shared.global [%0], [%1], 16;" :: "r"(smem_dst), "l"(gsrc));
}
#define CP_COMMIT() asm volatile("cp.async.commit_group;")
#define CP_WAIT0()  asm volatile("cp.async.wait_group 0;")

// ---- prep: exact XLA-order norms + per-point int8 quantization (k4-major) ----
__global__ void __launch_bounds__(256) prep_kernel(const float* __restrict__ pts) {
    int i = blockIdx.x * 256 + threadIdx.x;          // 0..32767
    int b = i >> 12, ptl = i & 4095;
    const float4* g4 = (const float4*)(pts + (size_t)i * CC);
    float v[64];
    float a[32];
    float mx = 0.0f;
    #pragma unroll
    for (int t = 0; t < 16; ++t) {
        float4 w = g4[t];
        v[4 * t] = w.x; v[4 * t + 1] = w.y; v[4 * t + 2] = w.z; v[4 * t + 3] = w.w;
        a[2 * t]     = __fadd_rn(__fmul_rn(w.x, w.x), __fmul_rn(w.y, w.y));
        a[2 * t + 1] = __fadd_rn(__fmul_rn(w.z, w.z), __fmul_rn(w.w, w.w));
        mx = fmaxf(mx, fmaxf(fmaxf(fabsf(w.x), fabsf(w.y)), fmaxf(fabsf(w.z), fabsf(w.w))));
    }
    #pragma unroll
    for (int off = 16; off >= 1; off >>= 1)
        #pragma unroll
        for (int l = 0; l < 16; ++l)
            if (l < off) a[l] = __fadd_rn(a[l], a[l + off]);
    g_sqc[i] = a[0];

    float inv = 127.0f / mx;
    g_scale[i] = mx * (1.0f / 127.0f);
    size_t tbase = ((size_t)b * 32 + (ptl >> 7)) * 16;
    #pragma unroll
    for (int t = 0; t < 16; ++t) {
        int q0 = max(-127, min(127, __float2int_rn(v[4 * t] * inv)));
        int q1 = max(-127, min(127, __float2int_rn(v[4 * t + 1] * inv)));
        int q2 = max(-127, min(127, __float2int_rn(v[4 * t + 2] * inv)));
        int q3 = max(-127, min(127, __float2int_rn(v[4 * t + 3] * inv)));
        u32 p = (u32)(q0 & 255) | ((u32)(q1 & 255) << 8) |
                ((u32)(q2 & 255) << 16) | ((u32)(q3 & 255) << 24);
        g_q8T[(tbase + t) * 128 + (ptl & 127)] = p;
    }
}

// ---- K1: dp4a int8 GEMM -> packed approx keys g_key[b][c][q] ----
__global__ void __launch_bounds__(256, 2)
adj_key_kernel()
{
    extern __shared__ char smem[];
    const u32 smb = (u32)__cvta_generic_to_shared(smem);
    u32* sA = (u32*)smem;
    u32* stage = (u32*)(smem + STG_);

    const int tid = threadIdx.x;
    const int b   = blockIdx.y;
    const int qt  = blockIdx.x;
    const int qbase = qt * 128;
    const int qg = tid >> 4;   // 0..15 : 8 queries
    const int cg = tid & 15;   // 0..15 : 8 candidates

    const char* q8B = (const char*)(g_q8T + (size_t)b * 32 * 2048);

    // initial loads: A tile, B tile 0, meta 0
    #pragma unroll
    for (int it = 0; it < 2; ++it) {
        int idx = it * 256 + tid;
        cpa16(smb + SA + idx * 16, q8B + (size_t)qt * 8192 + idx * 16);
        cpa16(smb + SB0 + idx * 16, q8B + idx * 16);
    }
    if (tid < 32)      cpa16(smb + SM0 + tid * 16, g_sqc + b * NN + tid * 4);
    else if (tid < 64) cpa16(smb + SM0 + 512 + (tid - 32) * 16, g_scale + b * NN + (tid - 32) * 4);
    CP_COMMIT();

    float sqQv[8], mQ[8];
    #pragma unroll
    for (int i = 0; i < 8; ++i) {
        sqQv[i] = __ldg(g_sqc + b * NN + qbase + qg * 8 + i);
        mQ[i]   = -2.0f * __ldg(g_scale + b * NN + qbase + qg * 8 + i);
    }

    CP_WAIT0();
    __syncthreads();

    u32* keyB = g_key + ((size_t)b << 24);

    for (int ct = 0; ct < NCT; ++ct) {
        const int cur = ct & 1;
        const int cbase = ct * 128;

        if (ct + 1 < NCT) {
            const u32 sbN = smb + (cur ? SB0 : SB1);
            const char* src = q8B + (size_t)(ct + 1) * 8192;
            #pragma unroll
            for (int it = 0; it < 2; ++it) {
                int idx = it * 256 + tid;
                cpa16(sbN + idx * 16, src + idx * 16);
            }
            const u32 smN = smb + (cur ? SM0 : SM1);
            if (tid < 32)
                cpa16(smN + tid * 16, g_sqc + b * NN + cbase + 128 + tid * 4);
            else if (tid < 64)
                cpa16(smN + 512 + (tid - 32) * 16, g_scale + b * NN + cbase + 128 + (tid - 32) * 4);
            CP_COMMIT();
        }

        // ---- dp4a GEMM: 8q x 8c per thread, K=64 (16 k4 groups)
        int acc[8][8];
        #pragma unroll
        for (int i = 0; i < 8; ++i)
            #pragma unroll
            for (int j = 0; j < 8; ++j) acc[i][j] = 0;

        const u32* sBc = (const u32*)(smem + (cur ? SB1 : SB0));
        #pragma unroll 4
        for (int k4 = 0; k4 < 16; ++k4) {
            uint4 a0 = *(const uint4*)(sA + k4 * 128 + qg * 8);
            uint4 a1 = *(const uint4*)(sA + k4 * 128 + qg * 8 + 4);
            uint4 b0 = *(const uint4*)(sBc + k4 * 128 + cg * 8);
            uint4 b1 = *(const uint4*)(sBc + k4 * 128 + cg * 8 + 4);
            u32 aq[8] = {a0.x, a0.y, a0.z, a0.w, a1.x, a1.y, a1.z, a1.w};
            u32 bc[8] = {b0.x, b0.y, b0.z, b0.w, b1.x, b1.y, b1.z, b1.w};
            #pragma unroll
            for (int i = 0; i < 8; ++i)
                #pragma unroll
                for (int j = 0; j < 8; ++j)
                    acc[i][j] = __dp4a((int)aq[i], (int)bc[j], acc[i][j]);
        }

        // ---- epilogue: approx adj -> packed key, staged transposed (swizzled)
        const float* sqcv = (const float*)(smem + (cur ? SM1 : SM0));
        const float* sCs  = sqcv + 128;
        #pragma unroll
        for (int j = 0; j < 8; ++j) {
            int c = cg * 8 + j;
            float scj = sqcv[c];
            float ssj = sCs[c];
            #pragma unroll
            for (int i = 0; i < 8; ++i) {
                float f = (float)acc[i][j];
                float adj = fmaf(mQ[i] * ssj, f, sqQv[i] + scj);
                u32 key = (ord32(adj) & 0xFFFFF000u) | (u32)(cbase + c);
                int q = qg * 8 + i;
                stage[c * 128 + (q ^ (cg << 2))] = key;
            }
        }
        __syncthreads();   // stage complete; B(cur)/meta(cur) reads done

        // coalesced key write: [c][q]
        #pragma unroll
        for (int it = 0; it < 16; ++it) {
            int idx = it * 256 + tid;
            int row = idx >> 5;
            int g4i = idx & 31;
            uint4 v = *(const uint4*)(stage + row * 128 + ((g4i ^ (row >> 3)) << 2));
            *(uint4*)(keyB + (((size_t)(cbase + row)) << 12) + qbase + g4i * 4) = v;
        }

        if (ct + 1 < NCT) CP_WAIT0();
        __syncthreads();
    }
}

// ---- K2: streaming approx top-48 filter on u32 keys ----
__global__ void __launch_bounds__(128)
select_kernel()
{
    __shared__ u32 topk[128 * KEXT];   // 24KB

    const int tid   = threadIdx.x;
    const int b     = blockIdx.y;
    const int qbase = blockIdx.x * 128;
    const int q     = qbase + tid;

    u32* row = topk + tid * KEXT;
    #pragma unroll
    for (int i = 0; i < KEXT; ++i) row[i] = 0xFFFFFFFFu;

    const u32* col = g_key + ((size_t)b << 24) + q;
    u32 thr = 0xFFFFFFFFu;

    u32 buf[4][8];
    #pragma unroll
    for (int pb = 0; pb < 3; ++pb)
        #pragma unroll
        for (int u = 0; u < 8; ++u)
            buf[pb][u] = col[(size_t)(pb * 8 + u) << 12];

    #pragma unroll 1
    for (int c8 = 0; c8 < NN; c8 += 8) {
        int stg = (c8 >> 3) & 3;
        if (c8 + 24 < NN) {
            int pre = (stg + 3) & 3;
            #pragma unroll
            for (int u = 0; u < 8; ++u)
                buf[pre][u] = col[(size_t)(c8 + 24 + u) << 12];
        }
        u32 av[8];
        #pragma unroll
        for (int u = 0; u < 8; ++u) av[u] = buf[stg][u];

        u32 mn = min(min(min(av[0], av[1]), min(av[2], av[3])),
                     min(min(av[4], av[5]), min(av[6], av[7])));
        if (mn >= thr) continue;
        #pragma unroll
        for (int u = 0; u < 8; ++u) {
            if (av[u] >= thr) continue;
            u32 key = av[u];
            if (key < row[KEXT - 1]) {
                int p = KEXT - 1;
                while (p > 0 && row[p - 1] > key) { row[p] = row[p - 1]; --p; }
                row[p] = key;
                thr = row[KEXT - 1];
            }
        }
    }

    u32* cd = g_cand + ((size_t)(b * NN + q)) * KEXT;
    #pragma unroll
    for (int i = 0; i < KEXT; ++i)
        cd[i] = row[i] & 0xFFFu;
}

// ---- K3: exact fp32 re-rank (bit-exact R2 keys), 4 threads/query ----
__global__ void __launch_bounds__(512)
rerank_kernel(const float* __restrict__ xyz,
              const float* __restrict__ pts,
              float* __restrict__ out)
{
    extern __shared__ char smem3[];
    u64*   keys = (u64*)(smem3 + R_KEYS);
    u64*   rows = (u64*)(smem3 + R_ROWS);
    float* sxq  = (float*)(smem3 + R_XQ);

    const int tid   = threadIdx.x;
    const int b     = blockIdx.y;
    const int qbase = blockIdx.x * 128;
    const float* ptsB = pts + (size_t)b * NN * CC;
    const float* sqB  = g_sqc + b * NN;

    // stage query tile
    #pragma unroll
    for (int it = 0; it < 4; ++it) {
        int idx = it * 512 + tid;
        int qrow = idx >> 4, g4i = idx & 15;
        float4 v = __ldg((const float4*)(ptsB + (size_t)(qbase + qrow) * CC) + g4i);
        *(float4*)(sxq + qrow * 64 + g4i * 4) = v;
    }
    __syncthreads();

    const int ql   = tid >> 2;
    const int slot = tid & 3;
    const int q    = qbase + ql;
    const float* xq = sxq + ql * 64;
    const float sqQ = __ldg(sqB + q);
    const u32* cd = g_cand + ((size_t)(b * NN + q)) * KEXT;

    #pragma unroll 1
    for (int jj = 0; jj < 12; ++jj) {
        int j = slot * 12 + jj;
        u32 idx = __ldg(cd + j);
        const float4* y4 = (const float4*)(ptsB + (size_t)idx * CC);
        float inner = 0.0f;
        #pragma unroll
        for (int blk = 0; blk < 4; ++blk) {
            float4 ya = __ldg(y4 + blk * 4);
            float4 yb = __ldg(y4 + blk * 4 + 1);
            float4 yc = __ldg(y4 + blk * 4 + 2);
            float4 yd = __ldg(y4 + blk * 4 + 3);
            float yv[16] = {ya.x, ya.y, ya.z, ya.w, yb.x, yb.y, yb.z, yb.w,
                            yc.x, yc.y, yc.z, yc.w, yd.x, yd.y, yd.z, yd.w};
            #pragma unroll
            for (int t = 0; t < 16; ++t)
                inner = fmaf(xq[blk * 16 + t], yv[t], inner);
        }
        float adj = __fadd_rn(fmaf(-2.0f, inner, sqQ), __ldg(sqB + idx));
        keys[ql * KEXT + j] = ((u64)ord32(adj) << 32) | idx;
    }
    __syncthreads();

    if (tid < 128) {
        u64* row = rows + tid * KD;
        #pragma unroll
        for (int i = 0; i < KD; ++i) row[i] = 0xFFFFFFFFFFFFFFFFull;
        u64 thr = 0xFFFFFFFFFFFFFFFFull;
        #pragma unroll 1
        for (int j = 0; j < KEXT; ++j) {
            u64 key = keys[tid * KEXT + j];
            if (key < thr) {
                int p = KD - 1;
                while (p > 0 && row[p - 1] > key) { row[p] = row[p - 1]; --p; }
                row[p] = key;
                thr = row[KD - 1];
            }
        }

        const int qq = qbase + tid;
        const float* xyzB = xyz + (size_t)b * NN * 3;
        const float* xb = xyzB + (size_t)qq * 3;
        float x0 = xb[0], x1 = xb[1], x2 = xb[2];
        float* o = out + (((size_t)b * NN + qq) * KOUT) * 10;
        #pragma unroll 4
        for (int j = 0; j < KOUT; ++j) {
            u32 idx = (u32)(row[2 * j] & 0xFFFFFFFFull);
            const float* nb = xyzB + (size_t)idx * 3;
            float n0 = nb[0], n1 = nb[1], n2 = nb[2];
            float r0 = x0 - n0, r1 = x1 - n1, r2 = x2 - n2;
            float d  = sqrtf(r0 * r0 + r1 * r1 + r2 * r2);
            float* oj = o + j * 10;
            oj[0] = d;
            oj[1] = r0; oj[2] = r1; oj[3] = r2;
            oj[4] = x0; oj[5] = x1; oj[6] = x2;
            oj[7] = n0; oj[8] = n1; oj[9] = n2;
        }
    }
}

extern "C" void kernel_launch(void* const* d_in, const int* in_sizes, int n_in,
                              void* d_out, int out_size) {
    const float* in0 = (const float*)d_in[0];
    const float* in1 = (const float*)d_in[1];
    const float* xyz;
    const float* pts;
    if (in_sizes[0] == BB * NN * 3) { xyz = in0; pts = in1; }
    else                            { xyz = in1; pts = in0; }

    cudaFuncSetAttribute(adj_key_kernel,
                         cudaFuncAttributeMaxDynamicSharedMemorySize, K1_SMEM);
    cudaFuncSetAttribute(rerank_kernel,
                         cudaFuncAttributeMaxDynamicSharedMemorySize, K3_SMEM);

    prep_kernel<<<BB * NN / 256, 256>>>(pts);

    dim3 g1(NN / 128, BB);
    adj_key_kernel<<<g1, 256, K1_SMEM>>>();
    select_kernel<<<g1, 128>>>();
    rerank_kernel<<<g1, 512, K3_SMEM>>>(xyz, pts, (float*)d_out);
}

// round 17
// speedup vs baseline: 1.2105x; 1.0232x over previous
#include <cuda_runtime.h>

#define BB      8
#define NN      4096
#define CC      64
#define KD      32
#define KEXT    48
#define KOUT    16
#define NCT     32

typedef unsigned int u32;
typedef unsigned long long u64;

// K1 smem layout (bytes)
#define SA      0        // A tile u32[16][128] = 8192
#define SB0     8192
#define SB1     16384
#define SM0     24576    // sqc 512 + scale 512
#define SM1     25600
#define STG_    26624    // stage u32[128][128] = 65536
#define K1_SMEM 92160

// K3 smem layout (bytes)
#define RSLOT   34816                // 128 rows * 68 floats * 4
#define SCAND   104448               // u32[128*48] = 24576
#define SKEYS   129024               // u64[128*49] = 50176
#define K3_SMEM 179200

__device__ float g_sqc[BB * NN];
__device__ float g_scale[BB * NN];
__device__ u32   g_q8T[(size_t)BB * NN * 16];        // [b][tile][k4][128] u32
__device__ u32   g_key[(size_t)BB * NN * NN];        // [b][c][q] packed keys
__device__ u32   g_cand[(size_t)BB * NN * KEXT];

__device__ __forceinline__ u32 ord32(float f) {
    u32 b = __float_as_uint(f);
    return b ^ ((b & 0x80000000u) ? 0xFFFFFFFFu : 0x80000000u);
}
__device__ __forceinline__ void cpa16(u32 smem_dst, const void* gsrc) {
    asm volatile("cp.async.cg.shared.global [%0], [%1], 16;" :: "r"(smem_dst), "l"(gsrc));
}
#define CP_COMMIT() asm volatile("cp.async.commit_group;")
#define CP_WAIT0()  asm volatile("cp.async.wait_group 0;")
#define CP_WAIT2()  asm volatile("cp.async.wait_group 2;")

// ---- prep: exact XLA-order norms + per-point int8 quantization (k4-major) ----
__global__ void __launch_bounds__(256) prep_kernel(const float* __restrict__ pts) {
    int i = blockIdx.x * 256 + threadIdx.x;
    int b = i >> 12, ptl = i & 4095;
    const float4* g4 = (const float4*)(pts + (size_t)i * CC);
    float v[64];
    float a[32];
    float mx = 0.0f;
    #pragma unroll
    for (int t = 0; t < 16; ++t) {
        float4 w = g4[t];
        v[4 * t] = w.x; v[4 * t + 1] = w.y; v[4 * t + 2] = w.z; v[4 * t + 3] = w.w;
        a[2 * t]     = __fadd_rn(__fmul_rn(w.x, w.x), __fmul_rn(w.y, w.y));
        a[2 * t + 1] = __fadd_rn(__fmul_rn(w.z, w.z), __fmul_rn(w.w, w.w));
        mx = fmaxf(mx, fmaxf(fmaxf(fabsf(w.x), fabsf(w.y)), fmaxf(fabsf(w.z), fabsf(w.w))));
    }
    #pragma unroll
    for (int off = 16; off >= 1; off >>= 1)
        #pragma unroll
        for (int l = 0; l < 16; ++l)
            if (l < off) a[l] = __fadd_rn(a[l], a[l + off]);
    g_sqc[i] = a[0];

    float inv = 127.0f / mx;
    g_scale[i] = mx * (1.0f / 127.0f);
    size_t tbase = ((size_t)b * 32 + (ptl >> 7)) * 16;
    #pragma unroll
    for (int t = 0; t < 16; ++t) {
        int q0 = max(-127, min(127, __float2int_rn(v[4 * t] * inv)));
        int q1 = max(-127, min(127, __float2int_rn(v[4 * t + 1] * inv)));
        int q2 = max(-127, min(127, __float2int_rn(v[4 * t + 2] * inv)));
        int q3 = max(-127, min(127, __float2int_rn(v[4 * t + 3] * inv)));
        u32 p = (u32)(q0 & 255) | ((u32)(q1 & 255) << 8) |
                ((u32)(q2 & 255) << 16) | ((u32)(q3 & 255) << 24);
        g_q8T[(tbase + t) * 128 + (ptl & 127)] = p;
    }
}

// ---- K1: dp4a int8 GEMM (512 thr, 4q x 8c, no spills) -> packed keys ----
__global__ void __launch_bounds__(512, 1)
adj_key_kernel()
{
    extern __shared__ char smem[];
    const u32 smb = (u32)__cvta_generic_to_shared(smem);
    u32* sA = (u32*)smem;
    u32* stage = (u32*)(smem + STG_);

    const int tid = threadIdx.x;
    const int b   = blockIdx.y;
    const int qt  = blockIdx.x;
    const int qbase = qt * 128;
    const int qg = tid >> 4;   // 0..31 : 4 queries each
    const int cg = tid & 15;   // 0..15 : 8 candidates each

    const char* q8B = (const char*)(g_q8T + (size_t)b * 32 * 2048);

    // A tile (8KB) + B tile 0 (8KB): 1 cpa16 each per thread
    cpa16(smb + SA + tid * 16, q8B + (size_t)qt * 8192 + tid * 16);
    cpa16(smb + SB0 + tid * 16, q8B + tid * 16);
    if (tid < 32)      cpa16(smb + SM0 + tid * 16, g_sqc + b * NN + tid * 4);
    else if (tid < 64) cpa16(smb + SM0 + 512 + (tid - 32) * 16, g_scale + b * NN + (tid - 32) * 4);
    CP_COMMIT();

    float sqQv[4], mQ[4];
    #pragma unroll
    for (int i = 0; i < 4; ++i) {
        sqQv[i] = __ldg(g_sqc + b * NN + qbase + qg * 4 + i);
        mQ[i]   = -2.0f * __ldg(g_scale + b * NN + qbase + qg * 4 + i);
    }

    CP_WAIT0();
    __syncthreads();

    u32* keyB = g_key + ((size_t)b << 24);

    for (int ct = 0; ct < NCT; ++ct) {
        const int cur = ct & 1;
        const int cbase = ct * 128;

        if (ct + 1 < NCT) {
            const u32 sbN = smb + (cur ? SB0 : SB1);
            cpa16(sbN + tid * 16, q8B + (size_t)(ct + 1) * 8192 + tid * 16);
            const u32 smN = smb + (cur ? SM0 : SM1);
            if (tid < 32)
                cpa16(smN + tid * 16, g_sqc + b * NN + cbase + 128 + tid * 4);
            else if (tid < 64)
                cpa16(smN + 512 + (tid - 32) * 16, g_scale + b * NN + cbase + 128 + (tid - 32) * 4);
            CP_COMMIT();
        }

        // ---- dp4a GEMM: 4q x 8c per thread, K=64 (16 k4 groups)
        int acc[4][8];
        #pragma unroll
        for (int i = 0; i < 4; ++i)
            #pragma unroll
            for (int j = 0; j < 8; ++j) acc[i][j] = 0;

        const u32* sBc = (const u32*)(smem + (cur ? SB1 : SB0));
        #pragma unroll 4
        for (int k4 = 0; k4 < 16; ++k4) {
            uint4 a0 = *(const uint4*)(sA + k4 * 128 + qg * 4);
            uint4 b0 = *(const uint4*)(sBc + k4 * 128 + cg * 8);
            uint4 b1 = *(const uint4*)(sBc + k4 * 128 + cg * 8 + 4);
            u32 aq[4] = {a0.x, a0.y, a0.z, a0.w};
            u32 bc[8] = {b0.x, b0.y, b0.z, b0.w, b1.x, b1.y, b1.z, b1.w};
            #pragma unroll
            for (int i = 0; i < 4; ++i)
                #pragma unroll
                for (int j = 0; j < 8; ++j)
                    acc[i][j] = __dp4a((int)aq[i], (int)bc[j], acc[i][j]);
        }

        // ---- epilogue: approx adj -> packed key, staged transposed (swizzled)
        const float* sqcv = (const float*)(smem + (cur ? SM1 : SM0));
        const float* sCs  = sqcv + 128;
        #pragma unroll
        for (int j = 0; j < 8; ++j) {
            int c = cg * 8 + j;
            float scj = sqcv[c];
            float ssj = sCs[c];
            #pragma unroll
            for (int i = 0; i < 4; ++i) {
                float f = (float)acc[i][j];
                float adj = fmaf(mQ[i] * ssj, f, sqQv[i] + scj);
                u32 key = (ord32(adj) & 0xFFFFF000u) | (u32)(cbase + c);
                int q = qg * 4 + i;
                stage[c * 128 + (q ^ (cg << 2))] = key;
            }
        }
        __syncthreads();

        // coalesced key write: [c][q], 8 uint4 per thread
        #pragma unroll
        for (int it = 0; it < 8; ++it) {
            int idx = it * 512 + tid;
            int row = idx >> 5;
            int g4i = idx & 31;
            uint4 v = *(const uint4*)(stage + row * 128 + ((g4i ^ (row >> 3)) << 2));
            *(uint4*)(keyB + (((size_t)(cbase + row)) << 12) + qbase + g4i * 4) = v;
        }

        if (ct + 1 < NCT) CP_WAIT0();
        __syncthreads();
    }
}

// ---- K2: streaming approx top-48 filter on u32 keys (unchanged) ----
__global__ void __launch_bounds__(128)
select_kernel()
{
    __shared__ u32 topk[128 * KEXT];

    const int tid   = threadIdx.x;
    const int b     = blockIdx.y;
    const int qbase = blockIdx.x * 128;
    const int q     = qbase + tid;

    u32* row = topk + tid * KEXT;
    #pragma unroll
    for (int i = 0; i < KEXT; ++i) row[i] = 0xFFFFFFFFu;

    const u32* col = g_key + ((size_t)b << 24) + q;
    u32 thr = 0xFFFFFFFFu;

    u32 buf[4][8];
    #pragma unroll
    for (int pb = 0; pb < 3; ++pb)
        #pragma unroll
        for (int u = 0; u < 8; ++u)
            buf[pb][u] = col[(size_t)(pb * 8 + u) << 12];

    #pragma unroll 1
    for (int c8 = 0; c8 < NN; c8 += 8) {
        int stg = (c8 >> 3) & 3;
        if (c8 + 24 < NN) {
            int pre = (stg + 3) & 3;
            #pragma unroll
            for (int u = 0; u < 8; ++u)
                buf[pre][u] = col[(size_t)(c8 + 24 + u) << 12];
        }
        u32 av[8];
        #pragma unroll
        for (int u = 0; u < 8; ++u) av[u] = buf[stg][u];

        u32 mn = min(min(min(av[0], av[1]), min(av[2], av[3])),
                     min(min(av[4], av[5]), min(av[6], av[7])));
        if (mn >= thr) continue;
        #pragma unroll
        for (int u = 0; u < 8; ++u) {
            if (av[u] >= thr) continue;
            u32 key = av[u];
            if (key < row[KEXT - 1]) {
                int p = KEXT - 1;
                while (p > 0 && row[p - 1] > key) { row[p] = row[p - 1]; --p; }
                row[p] = key;
                thr = row[KEXT - 1];
            }
        }
    }

    u32* cd = g_cand + ((size_t)(b * NN + q)) * KEXT;
    #pragma unroll
    for (int i = 0; i < KEXT; ++i)
        cd[i] = row[i] & 0xFFFu;
}

// ---- K3: warp-specialized exact re-rank (bit-exact R2 keys) + output ----
__global__ void __launch_bounds__(512, 1)
rerank_kernel(const float* __restrict__ xyz,
              const float* __restrict__ pts,
              float* __restrict__ out)
{
    extern __shared__ char smem3[];
    const u32 smb = (u32)__cvta_generic_to_shared(smem3);
    u32*   scand = (u32*)(smem3 + SCAND);
    u64*   keys  = (u64*)(smem3 + SKEYS);      // stride 49 per query

    const int tid   = threadIdx.x;
    const int b     = blockIdx.y;
    const int qbase = blockIdx.x * 128;
    const float* ptsB = pts + (size_t)b * NN * CC;
    const float* sqB  = g_sqc + b * NN;

    // candidate lists -> smem (coalesced)
    #pragma unroll
    for (int it = 0; it < 12; ++it) {
        int idx = it * 512 + tid;
        scand[idx] = g_cand[((size_t)(b * NN + qbase)) * KEXT + idx];
    }
    __syncthreads();

    // consumer state: query vector in registers
    float xq[CC];
    float sqQ = 0.0f;
    if (tid < 128) {
        const float4* g4 = (const float4*)(ptsB + (size_t)(qbase + tid) * CC);
        #pragma unroll
        for (int i = 0; i < 16; ++i) {
            float4 v = __ldg(g4 + i);
            xq[4 * i] = v.x; xq[4 * i + 1] = v.y; xq[4 * i + 2] = v.z; xq[4 * i + 3] = v.w;
        }
        sqQ = __ldg(sqB + qbase + tid);
    }

    // producer prologue: rounds 0 and 1
    #pragma unroll
    for (int pr = 0; pr < 2; ++pr) {
        if (tid >= 128) {
            int p = tid - 128;
            #pragma unroll
            for (int t = 0; t < 6; ++t) {
                int job = t * 384 + p;
                if (job < 2048) {
                    int rw = job >> 4, ch = job & 15;
                    u32 cidx = scand[rw * KEXT + pr];
                    cpa16(smb + (pr % 3) * RSLOT + rw * 272 + ch * 16,
                          (const char*)ptsB + (size_t)cidx * 256 + ch * 16);
                }
            }
        }
        CP_COMMIT();
    }

    #pragma unroll 1
    for (int j = 0; j < KEXT; ++j) {
        // issue round j+2
        if (tid >= 128 && j + 2 < KEXT) {
            int p = tid - 128;
            #pragma unroll
            for (int t = 0; t < 6; ++t) {
                int job = t * 384 + p;
                if (job < 2048) {
                    int rw = job >> 4, ch = job & 15;
                    u32 cidx = scand[rw * KEXT + j + 2];
                    cpa16(smb + ((j + 2) % 3) * RSLOT + rw * 272 + ch * 16,
                          (const char*)ptsB + (size_t)cidx * 256 + ch * 16);
                }
            }
        }
        CP_COMMIT();
        CP_WAIT2();
        __syncthreads();   // slot j ready

        if (tid < 128) {
            const float* rowp = (const float*)(smem3 + (j % 3) * RSLOT) + tid * 68;
            float inner = 0.0f;
            #pragma unroll
            for (int k4 = 0; k4 < 16; ++k4) {
                float4 y = *(const float4*)(rowp + k4 * 4);
                inner = fmaf(xq[4 * k4],     y.x, inner);
                inner = fmaf(xq[4 * k4 + 1], y.y, inner);
                inner = fmaf(xq[4 * k4 + 2], y.z, inner);
                inner = fmaf(xq[4 * k4 + 3], y.w, inner);
            }
            u32 cidx = scand[tid * KEXT + j];
            float adj = __fadd_rn(fmaf(-2.0f, inner, sqQ), __ldg(sqB + cidx));
            keys[tid * 49 + j] = ((u64)ord32(adj) << 32) | cidx;
        }
        __syncthreads();   // consumers done with slot j before round j+1 overwrites it
    }

    // merge + output (reuse ring memory for topk rows)
    u64* rows = (u64*)smem3;
    if (tid < 128) {
        u64* row = rows + tid * KD;
        #pragma unroll
        for (int i = 0; i < KD; ++i) row[i] = 0xFFFFFFFFFFFFFFFFull;
        u64 thr = 0xFFFFFFFFFFFFFFFFull;
        #pragma unroll 1
        for (int j = 0; j < KEXT; ++j) {
            u64 key = keys[tid * 49 + j];
            if (key < thr) {
                int p = KD - 1;
                while (p > 0 && row[p - 1] > key) { row[p] = row[p - 1]; --p; }
                row[p] = key;
                thr = row[KD - 1];
            }
        }

        const int qq = qbase + tid;
        const float* xyzB = xyz + (size_t)b * NN * 3;
        const float* xb = xyzB + (size_t)qq * 3;
        float x0 = xb[0], x1 = xb[1], x2 = xb[2];
        float* o = out + (((size_t)b * NN + qq) * KOUT) * 10;
        #pragma unroll 4
        for (int j = 0; j < KOUT; ++j) {
            u32 idx = (u32)(row[2 * j] & 0xFFFFFFFFull);
            const float* nb = xyzB + (size_t)idx * 3;
            float n0 = nb[0], n1 = nb[1], n2 = nb[2];
            float r0 = x0 - n0, r1 = x1 - n1, r2 = x2 - n2;
            float d  = sqrtf(r0 * r0 + r1 * r1 + r2 * r2);
            float* oj = o + j * 10;
            oj[0] = d;
            oj[1] = r0; oj[2] = r1; oj[3] = r2;
            oj[4] = x0; oj[5] = x1; oj[6] = x2;
            oj[7] = n0; oj[8] = n1; oj[9] = n2;
        }
    }
}

extern "C" void kernel_launch(void* const* d_in, const int* in_sizes, int n_in,
                              void* d_out, int out_size) {
    const float* in0 = (const float*)d_in[0];
    const float* in1 = (const float*)d_in[1];
    const float* xyz;
    const float* pts;
    if (in_sizes[0] == BB * NN * 3) { xyz = in0; pts = in1; }
    else                            { xyz = in1; pts = in0; }

    cudaFuncSetAttribute(adj_key_kernel,
                         cudaFuncAttributeMaxDynamicSharedMemorySize, K1_SMEM);
    cudaFuncSetAttribute(rerank_kernel,
                         cudaFuncAttributeMaxDynamicSharedMemorySize, K3_SMEM);

    prep_kernel<<<BB * NN / 256, 256>>>(pts);

    dim3 g1(NN / 128, BB);
    adj_key_kernel<<<g1, 512, K1_SMEM>>>();
    select_kernel<<<g1, 128>>>();
    rerank_kernel<<<g1, 512, K3_SMEM>>>(xyz, pts, (float*)d_out);
}